// round 6
// baseline (speedup 1.0000x reference)
#include <cuda_runtime.h>
#include <cuda_bf16.h>
#include <cstdint>
#include <math.h>

#define N_IN   8192
#define N_MC   32768
#define K_TOP  656
#define MASK_WORDS (N_IN / 32)          // 256
#define HPAD   257                      // bank-rotating pad: bank=(wid+bin)%32

__device__ float g_overlap[N_MC];

// ---------------------------------------------------------------------------
// Kernel 1 (fused): per-block mask build + overlap  — UNCHANGED (at roofline)
//   overlap_eff[row] = exp(na-dc) * popcount((perm_row >= 0.5) & I)
// 1024 threads/block, one warp per row, float4 .cs streaming. ~6.7 TB/s.
// ---------------------------------------------------------------------------
__global__ __launch_bounds__(1024) void overlap_kernel(
    const float* __restrict__ I,
    const float* __restrict__ perm,
    const float* __restrict__ duty,
    const float* __restrict__ navg)
{
    __shared__ uint32_t smask[MASK_WORDS];
    const int t    = threadIdx.x;
    const int warp = t >> 5;
    const int lane = t & 31;

    #pragma unroll
    for (int k2 = 0; k2 < 8; ++k2) {
        float v = I[k2 * 1024 + t];
        unsigned ball = __ballot_sync(0xffffffffu, v != 0.0f);
        if (lane == 0) smask[k2 * 32 + warp] = ball;
    }
    __syncthreads();

    const int row = blockIdx.x * 32 + warp;
    const float4* p = reinterpret_cast<const float4*>(perm + (size_t)row * N_IN);

    int cnt = 0;
    #pragma unroll 8
    for (int it = 0; it < 64; ++it) {
        int c4 = it * 32 + lane;
        float4 v = __ldcs(&p[c4]);
        int c = c4 * 4;
        uint32_t m = smask[c >> 5] >> (c & 31);
        cnt += ((m & 1u) && v.x >= 0.5f);
        cnt += ((m & 2u) && v.y >= 0.5f);
        cnt += ((m & 4u) && v.z >= 0.5f);
        cnt += ((m & 8u) && v.w >= 0.5f);
    }
    cnt = __reduce_add_sync(0xffffffffu, cnt);

    if (lane == 0) {
        float d = navg[row] - duty[row];
        float boost = (float)exp((double)d);     // correctly-rounded f32 exp
        g_overlap[row] = boost * (float)cnt;
    }
}

// ---------------------------------------------------------------------------
// Kernel 2: exact top-K (K=656), jax.lax.top_k tie semantics.
// Single block, 1024 threads, keys in registers (32/thread).
// 4 x 8-bit radix-select; per-warp PADDED histogram banks (conflict-free
// same-bin atomics); 3 barriers/pass: warp 0 scans+selects while warps
// 1-31 zero banks for the next pass.
// ---------------------------------------------------------------------------
__global__ __launch_bounds__(1024) void topk_kernel(float* __restrict__ out)
{
    __shared__ uint32_t s_hist[32][HPAD];   // padded banks (~32.9 KB)
    __shared__ uint32_t s_red[256];
    __shared__ uint32_t s_wtot[32];
    __shared__ uint32_t s_prefix;
    __shared__ int      s_rem;

    const int tid  = threadIdx.x;
    const int lane = tid & 31;
    const int wid  = tid >> 5;
    const int seg  = wid << 10;             // warp's 1024-key segment

    // keys -> registers (coalesced; overlaps >= 0 so u32 order == float order)
    uint32_t key[32];
    #pragma unroll
    for (int i = 0; i < 32; ++i)
        key[i] = __float_as_uint(g_overlap[seg + i * 32 + lane]);

    // zero banks once up front
    for (int z = tid; z < 32 * HPAD; z += 1024)
        ((uint32_t*)s_hist)[z] = 0u;
    if (tid == 0) { s_prefix = 0u; s_rem = K_TOP; }
    __syncthreads();

    // ---- radix select: find T = K-th largest key ----
    #pragma unroll
    for (int shift = 24; shift >= 0; shift -= 8) {
        const uint32_t prefix = s_prefix;

        #pragma unroll
        for (int i = 0; i < 32; ++i) {
            uint32_t k = key[i];
            bool cand = (shift == 24) || (((k ^ prefix) >> (shift + 8)) == 0u);
            unsigned amask = __ballot_sync(0xffffffffu, cand);
            if (cand) {
                uint32_t bin = (k >> shift) & 255u;
                unsigned peers = __match_any_sync(amask, bin);
                if (lane == (__ffs(peers) - 1))
                    atomicAdd(&s_hist[wid][bin], (uint32_t)__popc(peers));
            }
        }
        __syncthreads();

        // reduce 32 banks -> s_red[bin] (conflict-free; pad rotates banks)
        if (tid < 256) {
            uint32_t sum = 0;
            #pragma unroll
            for (int w = 0; w < 32; ++w) sum += s_hist[w][tid];
            s_red[tid] = sum;
        }
        __syncthreads();

        if (wid == 0) {
            // warp 0: suffix-scan over descending bins, 8 bins per lane
            uint32_t loc[8];
            uint32_t csum = 0;
            #pragma unroll
            for (int j = 0; j < 8; ++j) {
                loc[j] = s_red[255 - (lane * 8 + j)];
                csum += loc[j];
            }
            uint32_t inc = csum;
            #pragma unroll
            for (int off = 1; off < 32; off <<= 1) {
                uint32_t u = __shfl_up_sync(0xffffffffu, inc, off);
                if (lane >= off) inc += u;
            }
            uint32_t excl = inc - csum;
            int rem = s_rem;
            if ((int)excl < rem && (int)inc >= rem) {   // exactly one lane
                uint32_t cum = excl;
                #pragma unroll
                for (int j = 0; j < 8; ++j) {
                    cum += loc[j];
                    if ((int)cum >= rem) {
                        uint32_t b = (uint32_t)(255 - (lane * 8 + j));
                        s_prefix = prefix | (b << shift);
                        s_rem = rem - (int)(cum - loc[j]);
                        break;
                    }
                }
            }
        } else {
            // warps 1-31: zero banks for the next pass
            for (int z = tid - 32; z < 32 * HPAD; z += 992)
                ((uint32_t*)s_hist)[z] = 0u;
        }
        __syncthreads();
    }

    const uint32_t T = s_prefix;   // exact K-th largest key
    const int      r = s_rem;      // # of ==T entries to keep (lowest index)

    // ---- marking from registers: count, scan warp totals, mark ----
    int weq = 0;
    #pragma unroll
    for (int i = 0; i < 32; ++i)
        weq += __popc(__ballot_sync(0xffffffffu, key[i] == T));
    if (lane == 0) s_wtot[wid] = (uint32_t)weq;
    __syncthreads();

    if (wid == 0) {
        int v = (int)s_wtot[lane];
        #pragma unroll
        for (int off = 1; off < 32; off <<= 1) {
            int u = __shfl_up_sync(0xffffffffu, v, off);
            if (lane >= off) v += u;
        }
        s_wtot[lane] = (uint32_t)v;   // inclusive scan of warp totals
    }
    __syncthreads();

    int rank = (wid == 0) ? 0 : (int)s_wtot[wid - 1];
    #pragma unroll
    for (int i = 0; i < 32; ++i) {
        uint32_t k = key[i];
        bool eq = (k == T);
        unsigned ball = __ballot_sync(0xffffffffu, eq);
        int myrank = rank + __popc(ball & ((1u << lane) - 1u));
        out[seg + i * 32 + lane] = ((k > T) || (eq && myrank < r)) ? 1.0f : 0.0f;
        rank += __popc(ball);
    }
}

// ---------------------------------------------------------------------------
extern "C" void kernel_launch(void* const* d_in, const int* in_sizes, int n_in,
                              void* d_out, int out_size)
{
    const float* I    = (const float*)d_in[0];
    const float* perm = (const float*)d_in[1];
    const float* duty = (const float*)d_in[2];
    const float* navg = (const float*)d_in[3];
    float* out = (float*)d_out;

    (void)in_sizes; (void)n_in; (void)out_size;

    overlap_kernel<<<N_MC / 32, 1024>>>(I, perm, duty, navg);
    topk_kernel<<<1, 1024>>>(out);
}